// round 9
// baseline (speedup 1.0000x reference)
#include <cuda_runtime.h>
#include <cuda_fp16.h>
#include <cstdint>
#include <math.h>

#define T_STEPS 512
#define BATCH   256
#define IN_DIMV 129
#define HID     768
#define OUTD    128
#define XST     192
#define CHUNK   128
#define NCHK    6              // 768 / 128
#define NCTA    96             // 48 row tiles x 2 batch halves
#define DEC_T   256
#define KTILE   32

#define AST 136                // hx stage row stride (halves)
#define WST 776                // W smem row stride (halves)
#define WXS 216                // xproj W smem stride (halves)
#define STAGE_B 34816          // 128*136*2
#define SM_W_B  99328          // 64*776*2
#define SMEM_SZ (SM_W_B + 3 * STAGE_B)   // 203776

// ---------------- static device scratch ----------------
__device__ __align__(128) __half g_Wp [(size_t)3072 * HID];             // perm [row][k<768]
__device__ __align__(128) __half g_Wxp[(size_t)3072 * XST];             // perm [row][k xpart]
__device__ __align__(128) __half g_xbk[(size_t)T_STEPS * BATCH * XST];  // [t][b][k]
__device__ __align__(128) float  g_xp [(size_t)T_STEPS * 48 * 64 * 256];// [t][tile][col64][b256]
__device__ __align__(128) __half g_hbk[2 * BATCH * HID];                // ping-pong [b][k]
__device__ __align__(128) float  g_hist[(size_t)DEC_T * HID * BATCH];   // [t'][k][b] fp32
__device__ float g_bias[3072];
__device__ float g_WdecT[HID * OUTD];
__device__ int   g_flag[2][48];       // per-(bHalf,tile) monotonic step flags

// ---------------- helpers ----------------
__device__ __forceinline__ uint32_t smem_u32(const void* p) {
    uint32_t a;
    asm("{ .reg .u64 t; cvta.to.shared.u64 t, %1; cvt.u32.u64 %0, t; }" : "=r"(a) : "l"(p));
    return a;
}
__device__ __forceinline__ void cp16(uint32_t dst, const void* src) {
    asm volatile("cp.async.cg.shared.global [%0], [%1], 16;" :: "r"(dst), "l"(src));
}
__device__ __forceinline__ void cpcommit() { asm volatile("cp.async.commit_group;" ::: "memory"); }
template <int N> __device__ __forceinline__ void cpwait() {
    asm volatile("cp.async.wait_group %0;" :: "n"(N) : "memory");
}
#define LDSM4(r0, r1, r2, r3, addr) \
    asm volatile("ldmatrix.sync.aligned.m8n8.x4.shared.b16 {%0,%1,%2,%3}, [%4];" \
        : "=r"(r0), "=r"(r1), "=r"(r2), "=r"(r3) : "r"(addr))
__device__ __forceinline__ void mma16(float* d, const uint32_t* a, const uint32_t* b) {
    asm volatile("mma.sync.aligned.m16n8k16.row.col.f32.f16.f16.f32 "
        "{%0,%1,%2,%3}, {%4,%5,%6,%7}, {%8,%9}, {%0,%1,%2,%3};"
        : "+f"(d[0]), "+f"(d[1]), "+f"(d[2]), "+f"(d[3])
        : "r"(a[0]), "r"(a[1]), "r"(a[2]), "r"(a[3]), "r"(b[0]), "r"(b[1]));
}
__device__ __forceinline__ float tanha(float x) {
    float y; asm("tanh.approx.f32 %0, %1;" : "=f"(y) : "f"(x)); return y;
}
__device__ __forceinline__ float sigm(float x) { return fmaf(0.5f, tanha(0.5f * x), 0.5f); }
__device__ __forceinline__ void waitflag(const int* p, int t) {
    int v;
    do { asm volatile("ld.acquire.gpu.global.b32 %0, [%1];" : "=r"(v) : "l"(p)); } while (v < t);
}
__device__ __forceinline__ void postflag(int* p, int v) {
    asm volatile("st.release.gpu.global.b32 [%0], %1;" :: "l"(p), "r"(v) : "memory");
}

// ---------------- prep kernels ----------------
// perm row p = nTile*64 + wn*32 + nt*8 + w3  ->  orig gate(nt)*768 + unit
__global__ void prep_w_kernel(const float* __restrict__ Wih, const float* __restrict__ Whh,
                              const float* __restrict__ bih, const float* __restrict__ bhh) {
    int idx = blockIdx.x * blockDim.x + threadIdx.x;
    if (idx < 3072) {
        int nTile = idx >> 6, j = idx & 63;
        int wn = j >> 5, jj = j & 31, nt = jj >> 3, w3 = jj & 7;
        int orig = nt * HID + nTile * 16 + wn * 8 + w3;
        g_bias[idx] = bih[orig] + bhh[orig];
    }
    for (size_t ee = idx; ee < (size_t)3072 * HID; ee += (size_t)gridDim.x * blockDim.x) {
        int p = (int)(ee / HID), k = (int)(ee % HID);
        int nTile = p >> 6, j = p & 63;
        int wn = j >> 5, jj = j & 31, nt = jj >> 3, w3 = jj & 7;
        int orig = nt * HID + nTile * 16 + wn * 8 + w3;
        g_Wp[ee] = __float2half_rn(Whh[(size_t)orig * HID + k]);
    }
    for (size_t ee = idx; ee < (size_t)3072 * XST; ee += (size_t)gridDim.x * blockDim.x) {
        int p = (int)(ee / XST), k = (int)(ee % XST);
        int nTile = p >> 6, j = p & 63;
        int wn = j >> 5, jj = j & 31, nt = jj >> 3, w3 = jj & 7;
        int orig = nt * HID + nTile * 16 + wn * 8 + w3;
        g_Wxp[ee] = (k < IN_DIMV) ? __float2half_rn(Wih[(size_t)orig * IN_DIMV + k])
                                  : __ushort_as_half(0);
    }
}
__global__ void prep_x_kernel(const float* __restrict__ seq) {
    for (size_t e = blockIdx.x * blockDim.x + threadIdx.x;
         e < (size_t)T_STEPS * BATCH * XST; e += (size_t)gridDim.x * blockDim.x) {
        int k = (int)(e % XST);
        size_t tb = e / XST;
        g_xbk[e] = (k < IN_DIMV) ? __float2half_rn(seq[tb * IN_DIMV + k]) : __ushort_as_half(0);
    }
}
__global__ void zero_h_kernel() {
    int i = blockIdx.x * blockDim.x + threadIdx.x;
    if (i < 2 * BATCH * HID) g_hbk[i] = __ushort_as_half(0);
    if (i < 96) ((int*)g_flag)[i] = 0;
}
__global__ void transpose_wdec_kernel(const float* __restrict__ Wdec) {
    __shared__ float tile[32][33];
    int k0 = blockIdx.x * 32, o0 = blockIdx.y * 32;
    int tx = threadIdx.x, ty = threadIdx.y;
    #pragma unroll
    for (int i = 0; i < 32; i += 8)
        tile[ty + i][tx] = Wdec[(size_t)(o0 + ty + i) * HID + k0 + tx];
    __syncthreads();
    #pragma unroll
    for (int i = 0; i < 32; i += 8)
        g_WdecT[(size_t)(k0 + ty + i) * OUTD + o0 + tx] = tile[tx][ty + i];
}

// ---------------- xproj GEMM: g_xp = Wx * x for all t ----------------
__global__ void __launch_bounds__(256) xproj_kernel() {
    __shared__ __half sX[128 * 72];
    __shared__ __half sWx[64 * WXS];
    const int tid = threadIdx.x, lane = tid & 31, wid = tid >> 5;
    const int wm = wid & 3, wn = wid >> 2;
    const int tile = blockIdx.x >> 1, bHalf = blockIdx.x & 1, t = blockIdx.y;
    const int q = lane >> 2, rlk = lane & 3;

    for (int i = tid; i < 64 * 24; i += 256) {
        int r = i / 24, s = i % 24;
        *(uint4*)(sWx + r * WXS + s * 8) =
            *(const uint4*)(g_Wxp + (size_t)(tile * 64 + r) * XST + s * 8);
    }

    float d[2][4][4];
    #pragma unroll
    for (int mt = 0; mt < 2; mt++)
        #pragma unroll
        for (int nt = 0; nt < 4; nt++)
            #pragma unroll
            for (int j = 0; j < 4; j++) d[mt][nt][j] = 0.f;

    for (int c = 0; c < 3; c++) {
        __syncthreads();
        #pragma unroll
        for (int j = 0; j < 4; j++) {
            int s = j * 256 + tid, row = s >> 3, seg = s & 7;
            *(uint4*)(sX + row * 72 + seg * 8) =
                *(const uint4*)(g_xbk + ((size_t)t * BATCH + bHalf * 128 + row) * XST
                                + c * 64 + seg * 8);
        }
        __syncthreads();
        #pragma unroll
        for (int ks = 0; ks < 4; ks++) {
            const int kb = ks * 16, kw = c * 64 + kb;
            uint32_t a[2][4], b[4][2];
            #pragma unroll
            for (int mt = 0; mt < 2; mt++) {
                const int m0 = wm * 32 + mt * 16 + q;
                a[mt][0] = *(const uint32_t*)(sX + (m0)     * 72 + kb + 2 * rlk);
                a[mt][1] = *(const uint32_t*)(sX + (m0 + 8) * 72 + kb + 2 * rlk);
                a[mt][2] = *(const uint32_t*)(sX + (m0)     * 72 + kb + 2 * rlk + 8);
                a[mt][3] = *(const uint32_t*)(sX + (m0 + 8) * 72 + kb + 2 * rlk + 8);
            }
            #pragma unroll
            for (int nt = 0; nt < 4; nt++) {
                const int n0 = wn * 32 + nt * 8 + q;
                b[nt][0] = *(const uint32_t*)(sWx + n0 * WXS + kw + 2 * rlk);
                b[nt][1] = *(const uint32_t*)(sWx + n0 * WXS + kw + 2 * rlk + 8);
            }
            #pragma unroll
            for (int mt = 0; mt < 2; mt++)
                #pragma unroll
                for (int nt = 0; nt < 4; nt++)
                    mma16(d[mt][nt], a[mt], b[nt]);
        }
    }

    const size_t xb = ((size_t)t * 48 + tile) * 16384;
    #pragma unroll
    for (int mt = 0; mt < 2; mt++)
        #pragma unroll
        for (int nt = 0; nt < 4; nt++)
            #pragma unroll
            for (int j = 0; j < 4; j++) {
                int col = wn * 32 + nt * 8 + 2 * rlk + (j & 1);
                int bb  = bHalf * 128 + wm * 32 + mt * 16 + q + 8 * (j >> 1);
                g_xp[xb + (size_t)col * 256 + bb] = d[mt][nt][j];
            }
}

// ---------------- persistent fp16 tensor-core LSTM (dataflow sync) ----------
__global__ void __launch_bounds__(256, 1) lstm_mma_kernel() {
    extern __shared__ char smc[];
    __half* sW = (__half*)smc;                      // [64][776]
    const uint32_t sWu  = smem_u32(smc);
    const uint32_t sStU = sWu + SM_W_B;

    const int tid = threadIdx.x, lane = tid & 31, wid = tid >> 5;
    const int wm = wid & 3, wn = wid >> 2;          // 4 batch-warps x 2 row-warps
    const int cta = blockIdx.x, nTile = cta >> 1, bHalf = cta & 1;
    const int q = lane >> 2, rlk = lane & 3;
    const int ku0 = nTile * 16 + wn * 8 + rlk * 2;
    int* const myFlags = g_flag[bHalf];
    const int myTileOff = (tid & 15) >> 1;          // producer tile this thread's cp16s read

    // resident W tile (768 -> 776 restride)
    for (int i = tid; i < 64 * 96; i += 256) {
        int r = i / 96, s = i % 96;
        *(uint4*)(sW + r * WST + s * 8) =
            *(const uint4*)(g_Wp + (size_t)(nTile * 64 + r) * HID + s * 8);
    }

    float bias_r[4][2];
    #pragma unroll
    for (int nt = 0; nt < 4; nt++)
        #pragma unroll
        for (int e = 0; e < 2; e++)
            bias_r[nt][e] = g_bias[nTile * 64 + wn * 32 + nt * 8 + rlk * 2 + e];

    float cst[8];
    #pragma unroll
    for (int i = 0; i < 8; i++) cst[i] = 0.f;

    const int cprow0 = tid >> 4, cpseg = tid & 15;
    const int la = lane;
    const uint32_t offA0 = ((wm * 32 + (la & 7) + ((la >> 3) & 1) * 8) * AST
                            + ((la >> 4) & 1) * 8) * 2;
    const uint32_t offA1 = offA0 + 16 * AST * 2;
    const uint32_t offB0 = sWu + ((wn * 32 + (la & 7) + ((la >> 4) & 1) * 8) * WST
                            + ((la >> 3) & 1) * 8) * 2;
    const uint32_t offB1 = offB0 + 16 * WST * 2;

    float d[2][4][4];
    auto load_xp = [&](int tt) {
        const float* xp = g_xp + ((size_t)tt * 48 + nTile) * 16384;
        #pragma unroll
        for (int mt = 0; mt < 2; mt++)
            #pragma unroll
            for (int nt = 0; nt < 4; nt++)
                #pragma unroll
                for (int j = 0; j < 4; j++) {
                    int col = wn * 32 + nt * 8 + 2 * rlk + (j & 1);
                    int bb  = bHalf * 128 + wm * 32 + mt * 16 + q + 8 * (j >> 1);
                    d[mt][nt][j] = __ldg(xp + (size_t)col * 256 + bb);
                }
    };

    __syncthreads();
    load_xp(0);

    for (int t = 0; t < T_STEPS; t++) {
        const int rslot = t & 1, wslot = rslot ^ 1;
        const __half* hsrc = g_hbk + (size_t)(rslot * BATCH + bHalf * 128) * HID;

        auto issue = [&](int c) {
            waitflag(myFlags + c * 8 + myTileOff, t);   // h producer for this thread's slice
            const uint32_t dst0 = sStU + (c % 3) * STAGE_B;
            const __half* src = hsrc + c * CHUNK;
            #pragma unroll
            for (int j = 0; j < 8; j++) {
                int row = j * 16 + cprow0;
                cp16(dst0 + (row * AST + cpseg * 8) * 2, src + (size_t)row * HID + cpseg * 8);
            }
            cpcommit();
        };

        issue(0); issue(1);
        for (int c = 0; c < NCHK; c++) {
            if (c < NCHK - 1) cpwait<1>(); else cpwait<0>();
            __syncthreads();
            if (c + 2 < NCHK) issue(c + 2);

            const uint32_t sb = sStU + (c % 3) * STAGE_B;
            const uint32_t wb = c * (CHUNK * 2);
            #pragma unroll
            for (int ks = 0; ks < 8; ks++) {
                uint32_t a[2][4], b[4][2];
                LDSM4(a[0][0], a[0][1], a[0][2], a[0][3], sb + offA0 + ks * 32);
                LDSM4(a[1][0], a[1][1], a[1][2], a[1][3], sb + offA1 + ks * 32);
                LDSM4(b[0][0], b[0][1], b[1][0], b[1][1], offB0 + wb + ks * 32);
                LDSM4(b[2][0], b[2][1], b[3][0], b[3][1], offB1 + wb + ks * 32);
                #pragma unroll
                for (int mt = 0; mt < 2; mt++)
                    #pragma unroll
                    for (int nt = 0; nt < 4; nt++)
                        mma16(d[mt][nt], a[mt], b[nt]);
            }
        }

        // register-resident epilogue
        #pragma unroll
        for (int mt = 0; mt < 2; mt++) {
            #pragma unroll
            for (int h = 0; h < 2; h++) {
                float ho[2];
                #pragma unroll
                for (int e = 0; e < 2; e++) {
                    float xi = d[mt][0][2 * h + e] + bias_r[0][e];
                    float xf = d[mt][1][2 * h + e] + bias_r[1][e];
                    float xg = d[mt][2][2 * h + e] + bias_r[2][e];
                    float xo = d[mt][3][2 * h + e] + bias_r[3][e];
                    const int ci = mt * 4 + h * 2 + e;
                    float cv = fmaf(sigm(xf), cst[ci], sigm(xi) * tanha(xg));
                    cst[ci] = cv;
                    ho[e] = sigm(xo) * tanha(cv);
                }
                const int bb = bHalf * 128 + wm * 32 + mt * 16 + q + 8 * h;
                *(__half2*)(g_hbk + ((size_t)wslot * BATCH + bb) * HID + ku0) =
                    __floats2half2_rn(ho[0], ho[1]);
                if (t >= DEC_T) {
                    const size_t hb = (size_t)(t - DEC_T) * (HID * BATCH);
                    g_hist[hb + (size_t)(ku0)     * BATCH + bb] = ho[0];
                    g_hist[hb + (size_t)(ku0 + 1) * BATCH + bb] = ho[1];
                }
            }
        }
        __threadfence();
        __syncthreads();
        if (tid == 0) postflag(&myFlags[nTile], t + 1);  // h_t published
        if (t + 1 < T_STEPS) load_xp(t + 1);             // overlaps peers' catch-up
    }
}

// ---------------- decoder GEMM: out[t][b][o] ----------------
__global__ void __launch_bounds__(256)
decode_kernel(const float* __restrict__ bdec, float* __restrict__ out) {
    __shared__ float wt[KTILE * 32];
    const int og = blockIdx.x, t = blockIdx.y, tid = threadIdx.x;
    float acc[32];
    #pragma unroll
    for (int i = 0; i < 32; i++) acc[i] = 0.f;
    for (int kt = 0; kt < HID / KTILE; kt++) {
        const int k0 = kt * KTILE;
        #pragma unroll
        for (int i = 0; i < 4; i++) {
            int e = i * 256 + tid, kk = e >> 5, oo = e & 31;
            wt[e] = g_WdecT[(size_t)(k0 + kk) * OUTD + og * 32 + oo];
        }
        __syncthreads();
        #pragma unroll 8
        for (int kk = 0; kk < KTILE; kk++) {
            float hv = g_hist[((size_t)t * HID + k0 + kk) * BATCH + tid];
            #pragma unroll
            for (int o4 = 0; o4 < 8; o4++) {
                float4 w = *(const float4*)&wt[kk * 32 + o4 * 4];
                acc[o4 * 4 + 0] += hv * w.x;  acc[o4 * 4 + 1] += hv * w.y;
                acc[o4 * 4 + 2] += hv * w.z;  acc[o4 * 4 + 3] += hv * w.w;
            }
        }
        __syncthreads();
    }
    size_t ob = ((size_t)t * BATCH + tid) * OUTD + og * 32;
    #pragma unroll
    for (int o4 = 0; o4 < 8; o4++) {
        float4 r;
        r.x = acc[o4 * 4 + 0] + bdec[og * 32 + o4 * 4 + 0];
        r.y = acc[o4 * 4 + 1] + bdec[og * 32 + o4 * 4 + 1];
        r.z = acc[o4 * 4 + 2] + bdec[og * 32 + o4 * 4 + 2];
        r.w = acc[o4 * 4 + 3] + bdec[og * 32 + o4 * 4 + 3];
        *(float4*)&out[ob + o4 * 4] = r;
    }
}

// ---------------- launch ----------------
extern "C" void kernel_launch(void* const* d_in, const int* in_sizes, int n_in,
                              void* d_out, int out_size) {
    const float* seq  = (const float*)d_in[0];
    const float* Wih  = (const float*)d_in[1];
    const float* Whh  = (const float*)d_in[2];
    const float* bih  = (const float*)d_in[3];
    const float* bhh  = (const float*)d_in[4];
    const float* Wdec = (const float*)d_in[5];
    const float* bdec = (const float*)d_in[6];
    float* out = (float*)d_out;

    cudaFuncSetAttribute(lstm_mma_kernel, cudaFuncAttributeMaxDynamicSharedMemorySize, SMEM_SZ);

    zero_h_kernel<<<(2 * BATCH * HID + 255) / 256, 256>>>();
    prep_w_kernel<<<512, 256>>>(Wih, Whh, bih, bhh);
    prep_x_kernel<<<2048, 256>>>(seq);
    dim3 tb(32, 8);
    transpose_wdec_kernel<<<dim3(HID / 32, OUTD / 32), tb>>>(Wdec);
    xproj_kernel<<<dim3(96, T_STEPS), 256>>>();
    lstm_mma_kernel<<<NCTA, 256, SMEM_SZ>>>();
    decode_kernel<<<dim3(4, DEC_T), 256>>>(bdec, out);
}

// round 10
// speedup vs baseline: 1.0063x; 1.0063x over previous
#include <cuda_runtime.h>
#include <cuda_fp16.h>
#include <cstdint>
#include <math.h>

#define T_STEPS 512
#define BATCH   256
#define IN_DIMV 129
#define HID     768
#define OUTD    128
#define XST     192
#define CHUNK   128
#define NCHK    6              // 768 / 128
#define NCTA    96             // 48 row tiles x 2 batch halves
#define THREADS 512
#define DEC_T   256
#define KTILE   32

#define AST 136                // hx stage row stride (halves)
#define WST 776                // W smem row stride (halves)
#define WXS 216                // xproj W smem stride (halves)
#define STAGE_B 34816          // 128*136*2
#define SM_W_B  99328          // 64*776*2
#define SMEM_SZ (SM_W_B + 3 * STAGE_B)   // 203776

// ---------------- static device scratch ----------------
__device__ __align__(128) __half g_Wp [(size_t)3072 * HID];             // perm [row][k]
__device__ __align__(128) __half g_Wxp[(size_t)3072 * XST];             // perm [row][k xpart]
__device__ __align__(128) __half g_xbk[(size_t)T_STEPS * BATCH * XST];  // [t][b][k]
__device__ __align__(128) float  g_xp [(size_t)T_STEPS * 48 * 64 * 256];// [t][tile][col][b]
__device__ __align__(128) __half g_hall[(size_t)(T_STEPS + 1) * BATCH * HID]; // [slice][b][k]
__device__ float g_bias[3072];
__device__ float g_WdecT[HID * OUTD];
__device__ unsigned g_barcnt;
__device__ unsigned g_bargen;

// ---------------- helpers ----------------
__device__ __forceinline__ uint32_t smem_u32(const void* p) {
    uint32_t a;
    asm("{ .reg .u64 t; cvta.to.shared.u64 t, %1; cvt.u32.u64 %0, t; }" : "=r"(a) : "l"(p));
    return a;
}
__device__ __forceinline__ void cp16(uint32_t dst, const void* src) {
    asm volatile("cp.async.cg.shared.global [%0], [%1], 16;" :: "r"(dst), "l"(src));
}
__device__ __forceinline__ void cpcommit() { asm volatile("cp.async.commit_group;" ::: "memory"); }
template <int N> __device__ __forceinline__ void cpwait() {
    asm volatile("cp.async.wait_group %0;" :: "n"(N) : "memory");
}
#define LDSM4(r0, r1, r2, r3, addr) \
    asm volatile("ldmatrix.sync.aligned.m8n8.x4.shared.b16 {%0,%1,%2,%3}, [%4];" \
        : "=r"(r0), "=r"(r1), "=r"(r2), "=r"(r3) : "r"(addr))
__device__ __forceinline__ void mma16(float* d, const uint32_t* a, const uint32_t* b) {
    asm volatile("mma.sync.aligned.m16n8k16.row.col.f32.f16.f16.f32 "
        "{%0,%1,%2,%3}, {%4,%5,%6,%7}, {%8,%9}, {%0,%1,%2,%3};"
        : "+f"(d[0]), "+f"(d[1]), "+f"(d[2]), "+f"(d[3])
        : "r"(a[0]), "r"(a[1]), "r"(a[2]), "r"(a[3]), "r"(b[0]), "r"(b[1]));
}
__device__ __forceinline__ float tanha(float x) {
    float y; asm("tanh.approx.f32 %0, %1;" : "=f"(y) : "f"(x)); return y;
}
__device__ __forceinline__ float sigm(float x) { return fmaf(0.5f, tanha(0.5f * x), 0.5f); }

// ---------------- grid barrier (96 CTAs, all resident at 1/SM) ----------------
__device__ __forceinline__ void gridbar() {
    __syncthreads();
    if (threadIdx.x == 0) {
        __threadfence();
        unsigned gen = *(volatile unsigned*)&g_bargen;
        if (atomicAdd(&g_barcnt, 1u) == NCTA - 1u) {
            atomicExch(&g_barcnt, 0u);
            __threadfence();
            atomicAdd(&g_bargen, 1u);
        } else {
            while (*(volatile unsigned*)&g_bargen == gen) { }
        }
        __threadfence();
    }
    __syncthreads();
}

// ---------------- prep kernels ----------------
// perm row p = nTile*64 + wn*16 + nt*8 + rlk*2 + e
//   gate = nt*2 + e (i,f,g,o) ; unit = nTile*16 + wn*4 + rlk
__device__ __forceinline__ int perm_to_orig(int p) {
    int nTile = p >> 6, j = p & 63;
    int wn = j >> 4, jj = j & 15, nt = jj >> 3, rr = jj & 7, rlk = rr >> 1, e = rr & 1;
    int gate = nt * 2 + e;
    int unit = nTile * 16 + wn * 4 + rlk;
    return gate * HID + unit;
}
__global__ void prep_w_kernel(const float* __restrict__ Wih, const float* __restrict__ Whh,
                              const float* __restrict__ bih, const float* __restrict__ bhh) {
    int idx = blockIdx.x * blockDim.x + threadIdx.x;
    if (idx < 3072) {
        int orig = perm_to_orig(idx);
        g_bias[idx] = bih[orig] + bhh[orig];
    }
    for (size_t ee = idx; ee < (size_t)3072 * HID; ee += (size_t)gridDim.x * blockDim.x) {
        int p = (int)(ee / HID), k = (int)(ee % HID);
        int orig = perm_to_orig(p);
        g_Wp[ee] = __float2half_rn(Whh[(size_t)orig * HID + k]);
    }
    for (size_t ee = idx; ee < (size_t)3072 * XST; ee += (size_t)gridDim.x * blockDim.x) {
        int p = (int)(ee / XST), k = (int)(ee % XST);
        int orig = perm_to_orig(p);
        g_Wxp[ee] = (k < IN_DIMV) ? __float2half_rn(Wih[(size_t)orig * IN_DIMV + k])
                                  : __ushort_as_half(0);
    }
}
__global__ void prep_x_kernel(const float* __restrict__ seq) {
    for (size_t e = blockIdx.x * blockDim.x + threadIdx.x;
         e < (size_t)T_STEPS * BATCH * XST; e += (size_t)gridDim.x * blockDim.x) {
        int k = (int)(e % XST);
        size_t tb = e / XST;
        g_xbk[e] = (k < IN_DIMV) ? __float2half_rn(seq[tb * IN_DIMV + k]) : __ushort_as_half(0);
    }
}
__global__ void zero_h_kernel() {     // zero slice 0 of g_hall (h_{-1} = 0)
    int i = blockIdx.x * blockDim.x + threadIdx.x;
    if (i < BATCH * HID) g_hall[i] = __ushort_as_half(0);
}
__global__ void transpose_wdec_kernel(const float* __restrict__ Wdec) {
    __shared__ float tile[32][33];
    int k0 = blockIdx.x * 32, o0 = blockIdx.y * 32;
    int tx = threadIdx.x, ty = threadIdx.y;
    #pragma unroll
    for (int i = 0; i < 32; i += 8)
        tile[ty + i][tx] = Wdec[(size_t)(o0 + ty + i) * HID + k0 + tx];
    __syncthreads();
    #pragma unroll
    for (int i = 0; i < 32; i += 8)
        g_WdecT[(size_t)(k0 + ty + i) * OUTD + o0 + tx] = tile[tx][ty + i];
}

// ---------------- xproj GEMM: g_xp[t][tile][col][b] = Wx * x ----------------
__global__ void __launch_bounds__(256) xproj_kernel() {
    __shared__ __half sX[128 * 72];
    __shared__ __half sWx[64 * WXS];
    const int tid = threadIdx.x, lane = tid & 31, wid = tid >> 5;
    const int wm = wid & 3, wn = wid >> 2;
    const int tile = blockIdx.x >> 1, bHalf = blockIdx.x & 1, t = blockIdx.y;
    const int q = lane >> 2, rlk = lane & 3;

    for (int i = tid; i < 64 * 24; i += 256) {
        int r = i / 24, s = i % 24;
        *(uint4*)(sWx + r * WXS + s * 8) =
            *(const uint4*)(g_Wxp + (size_t)(tile * 64 + r) * XST + s * 8);
    }

    float d[2][4][4];
    #pragma unroll
    for (int mt = 0; mt < 2; mt++)
        #pragma unroll
        for (int nt = 0; nt < 4; nt++)
            #pragma unroll
            for (int j = 0; j < 4; j++) d[mt][nt][j] = 0.f;

    for (int c = 0; c < 3; c++) {
        __syncthreads();
        #pragma unroll
        for (int j = 0; j < 4; j++) {
            int s = j * 256 + tid, row = s >> 3, seg = s & 7;
            *(uint4*)(sX + row * 72 + seg * 8) =
                *(const uint4*)(g_xbk + ((size_t)t * BATCH + bHalf * 128 + row) * XST
                                + c * 64 + seg * 8);
        }
        __syncthreads();
        #pragma unroll
        for (int ks = 0; ks < 4; ks++) {
            const int kb = ks * 16, kw = c * 64 + kb;
            uint32_t a[2][4], b[4][2];
            #pragma unroll
            for (int mt = 0; mt < 2; mt++) {
                const int m0 = wm * 32 + mt * 16 + q;
                a[mt][0] = *(const uint32_t*)(sX + (m0)     * 72 + kb + 2 * rlk);
                a[mt][1] = *(const uint32_t*)(sX + (m0 + 8) * 72 + kb + 2 * rlk);
                a[mt][2] = *(const uint32_t*)(sX + (m0)     * 72 + kb + 2 * rlk + 8);
                a[mt][3] = *(const uint32_t*)(sX + (m0 + 8) * 72 + kb + 2 * rlk + 8);
            }
            #pragma unroll
            for (int nt = 0; nt < 4; nt++) {
                const int n0 = wn * 32 + nt * 8 + q;
                b[nt][0] = *(const uint32_t*)(sWx + n0 * WXS + kw + 2 * rlk);
                b[nt][1] = *(const uint32_t*)(sWx + n0 * WXS + kw + 2 * rlk + 8);
            }
            #pragma unroll
            for (int mt = 0; mt < 2; mt++)
                #pragma unroll
                for (int nt = 0; nt < 4; nt++)
                    mma16(d[mt][nt], a[mt], b[nt]);
        }
    }

    const size_t xb = ((size_t)t * 48 + tile) * 16384;
    #pragma unroll
    for (int mt = 0; mt < 2; mt++)
        #pragma unroll
        for (int nt = 0; nt < 4; nt++)
            #pragma unroll
            for (int j = 0; j < 4; j++) {
                int col = wn * 32 + nt * 8 + 2 * rlk + (j & 1);
                int bb  = bHalf * 128 + wm * 32 + mt * 16 + q + 8 * (j >> 1);
                g_xp[xb + (size_t)col * 256 + bb] = d[mt][nt][j];
            }
}

// ---------------- persistent fp16 tensor-core LSTM (512 threads) ------------
__global__ void __launch_bounds__(THREADS, 1) lstm_mma_kernel() {
    extern __shared__ char smc[];
    __half* sW = (__half*)smc;                      // [64][776]
    const uint32_t sWu  = smem_u32(smc);
    const uint32_t sStU = sWu + SM_W_B;

    const int tid = threadIdx.x, lane = tid & 31, wid = tid >> 5;
    const int wm = wid & 3, wn = wid >> 2;          // 4 batch-warps x 4 row-warps(16)
    const int cta = blockIdx.x, nTile = cta >> 1, bHalf = cta & 1;
    const int q = lane >> 2, rlk = lane & 3;
    const int myUnit = nTile * 16 + wn * 4 + rlk;   // global k index of owned unit

    // resident W tile (768 -> 776 restride)
    for (int i = tid; i < 64 * 96; i += THREADS) {
        int r = i / 96, s = i % 96;
        *(uint4*)(sW + r * WST + s * 8) =
            *(const uint4*)(g_Wp + (size_t)(nTile * 64 + r) * HID + s * 8);
    }

    float br[2][2];                                  // [nt][e] -> gates i,f,g,o
    #pragma unroll
    for (int nt = 0; nt < 2; nt++)
        #pragma unroll
        for (int e = 0; e < 2; e++)
            br[nt][e] = g_bias[nTile * 64 + wn * 16 + nt * 8 + rlk * 2 + e];

    float cst[4];
    #pragma unroll
    for (int i = 0; i < 4; i++) cst[i] = 0.f;

    // cp.async: 2048 x 16B per chunk / 512 threads = 4 each
    const int cprow0 = tid >> 4, cpseg = tid & 15;
    // ldmatrix per-lane byte offsets
    const int la = lane;
    const uint32_t offA0 = ((wm * 32 + (la & 7) + ((la >> 3) & 1) * 8) * AST
                            + ((la >> 4) & 1) * 8) * 2;
    const uint32_t offA1 = offA0 + 16 * AST * 2;
    const uint32_t offB  = sWu + ((wn * 16 + (la & 7) + ((la >> 4) & 1) * 8) * WST
                            + ((la >> 3) & 1) * 8) * 2;

    float d[2][2][4];
    auto load_xp = [&](int tt) {
        const float* xp = g_xp + ((size_t)tt * 48 + nTile) * 16384;
        #pragma unroll
        for (int mt = 0; mt < 2; mt++)
            #pragma unroll
            for (int nt = 0; nt < 2; nt++)
                #pragma unroll
                for (int j = 0; j < 4; j++) {
                    int col = wn * 16 + nt * 8 + 2 * rlk + (j & 1);
                    int bb  = bHalf * 128 + wm * 32 + mt * 16 + q + 8 * (j >> 1);
                    d[mt][nt][j] = __ldg(xp + (size_t)col * 256 + bb);
                }
    };

    __syncthreads();
    load_xp(0);

    for (int t = 0; t < T_STEPS; t++) {
        const __half* hsrc = g_hall + (size_t)(t * BATCH + bHalf * 128) * HID;

        auto issue = [&](int c) {
            const uint32_t dst0 = sStU + (c % 3) * STAGE_B;
            const __half* src = hsrc + c * CHUNK;
            #pragma unroll
            for (int j = 0; j < 4; j++) {
                int row = j * 32 + cprow0;
                cp16(dst0 + (row * AST + cpseg * 8) * 2, src + (size_t)row * HID + cpseg * 8);
            }
            cpcommit();
        };

        issue(0); issue(1);
        for (int c = 0; c < NCHK; c++) {
            if (c < NCHK - 1) cpwait<1>(); else cpwait<0>();
            __syncthreads();
            if (c + 2 < NCHK) issue(c + 2);

            const uint32_t sb = sStU + (c % 3) * STAGE_B;
            const uint32_t wb = c * (CHUNK * 2);
            #pragma unroll
            for (int ks = 0; ks < 8; ks++) {
                uint32_t a[2][4], b[2][2];
                LDSM4(a[0][0], a[0][1], a[0][2], a[0][3], sb + offA0 + ks * 32);
                LDSM4(a[1][0], a[1][1], a[1][2], a[1][3], sb + offA1 + ks * 32);
                LDSM4(b[0][0], b[0][1], b[1][0], b[1][1], offB + wb + ks * 32);
                #pragma unroll
                for (int mt = 0; mt < 2; mt++)
                    #pragma unroll
                    for (int nt = 0; nt < 2; nt++)
                        mma16(d[mt][nt], a[mt], b[nt]);
            }
        }

        // register epilogue: this thread's accum cols = 4 gates of myUnit
        __half* hdst = g_hall + (size_t)(t + 1) * (BATCH * HID);
        #pragma unroll
        for (int mt = 0; mt < 2; mt++) {
            #pragma unroll
            for (int h = 0; h < 2; h++) {
                float xi = d[mt][0][2 * h + 0] + br[0][0];
                float xf = d[mt][0][2 * h + 1] + br[0][1];
                float xg = d[mt][1][2 * h + 0] + br[1][0];
                float xo = d[mt][1][2 * h + 1] + br[1][1];
                const int ci = mt * 2 + h;
                float cv = fmaf(sigm(xf), cst[ci], sigm(xi) * tanha(xg));
                cst[ci] = cv;
                float ho = sigm(xo) * tanha(cv);
                const int bb = bHalf * 128 + wm * 32 + mt * 16 + q + 8 * h;
                hdst[(size_t)bb * HID + myUnit] = __float2half_rn(ho);
            }
        }
        if (t + 1 < T_STEPS) load_xp(t + 1);   // hidden behind barrier
        gridbar();
    }
}

// ---------------- decoder GEMM: out[t][b][o], h from g_hall fp16 ------------
__global__ void __launch_bounds__(256)
decode_kernel(const float* __restrict__ bdec, float* __restrict__ out) {
    __shared__ float wt[KTILE * 32];
    const int og = blockIdx.x, t = blockIdx.y, tid = threadIdx.x;
    const __half* hrow = g_hall + ((size_t)(t + DEC_T + 1) * BATCH + tid) * HID;
    float acc[32];
    #pragma unroll
    for (int i = 0; i < 32; i++) acc[i] = 0.f;
    for (int kt = 0; kt < HID / KTILE; kt++) {
        const int k0 = kt * KTILE;
        #pragma unroll
        for (int i = 0; i < 4; i++) {
            int e = i * 256 + tid, kk = e >> 5, oo = e & 31;
            wt[e] = g_WdecT[(size_t)(k0 + kk) * OUTD + og * 32 + oo];
        }
        __syncthreads();
        __half hh[KTILE];
        #pragma unroll
        for (int i = 0; i < 4; i++)
            *(uint4*)&hh[i * 8] = *(const uint4*)(hrow + k0 + i * 8);
        #pragma unroll 8
        for (int kk = 0; kk < KTILE; kk++) {
            float hv = __half2float(hh[kk]);
            #pragma unroll
            for (int o4 = 0; o4 < 8; o4++) {
                float4 w = *(const float4*)&wt[kk * 32 + o4 * 4];
                acc[o4 * 4 + 0] += hv * w.x;  acc[o4 * 4 + 1] += hv * w.y;
                acc[o4 * 4 + 2] += hv * w.z;  acc[o4 * 4 + 3] += hv * w.w;
            }
        }
        __syncthreads();
    }
    size_t ob = ((size_t)t * BATCH + tid) * OUTD + og * 32;
    #pragma unroll
    for (int o4 = 0; o4 < 8; o4++) {
        float4 r;
        r.x = acc[o4 * 4 + 0] + bdec[og * 32 + o4 * 4 + 0];
        r.y = acc[o4 * 4 + 1] + bdec[og * 32 + o4 * 4 + 1];
        r.z = acc[o4 * 4 + 2] + bdec[og * 32 + o4 * 4 + 2];
        r.w = acc[o4 * 4 + 3] + bdec[og * 32 + o4 * 4 + 3];
        *(float4*)&out[ob + o4 * 4] = r;
    }
}

// ---------------- launch ----------------
extern "C" void kernel_launch(void* const* d_in, const int* in_sizes, int n_in,
                              void* d_out, int out_size) {
    const float* seq  = (const float*)d_in[0];
    const float* Wih  = (const float*)d_in[1];
    const float* Whh  = (const float*)d_in[2];
    const float* bih  = (const float*)d_in[3];
    const float* bhh  = (const float*)d_in[4];
    const float* Wdec = (const float*)d_in[5];
    const float* bdec = (const float*)d_in[6];
    float* out = (float*)d_out;

    cudaFuncSetAttribute(lstm_mma_kernel, cudaFuncAttributeMaxDynamicSharedMemorySize, SMEM_SZ);

    zero_h_kernel<<<(BATCH * HID + 255) / 256, 256>>>();
    prep_w_kernel<<<512, 256>>>(Wih, Whh, bih, bhh);
    prep_x_kernel<<<2048, 256>>>(seq);
    dim3 tb(32, 8);
    transpose_wdec_kernel<<<dim3(HID / 32, OUTD / 32), tb>>>(Wdec);
    xproj_kernel<<<dim3(96, T_STEPS), 256>>>();
    lstm_mma_kernel<<<NCTA, THREADS, SMEM_SZ>>>();
    decode_kernel<<<dim3(4, DEC_T), 256>>>(bdec, out);
}

// round 11
// speedup vs baseline: 1.2569x; 1.2490x over previous
#include <cuda_runtime.h>
#include <cuda_fp16.h>
#include <cstdint>
#include <math.h>

#define T_STEPS 512
#define BATCH   256
#define IN_DIMV 129
#define HID     768
#define OUTD    128
#define XST     192
#define CHUNK   96
#define NCHK    8              // 768 / 96
#define NCTA    128            // 32 row-tiles(96) x 4 batch-tiles(64)
#define THREADS 384
#define DEC_T   256
#define KTILE   32

#define AST 104                // hx stage row stride (halves): 96+8
#define WST 776                // W smem row stride (halves)
#define WXS 216                // xproj W smem stride (halves)
#define STAGE_B 13312          // 64*104*2
#define SM_W_B  148992         // 96*776*2
#define SMEM_SZ (SM_W_B + 3 * STAGE_B)   // 188928

// ---------------- static device scratch ----------------
__device__ __align__(128) __half g_Wp [(size_t)3072 * HID];             // perm [row][k]
__device__ __align__(128) __half g_Wxp[(size_t)3072 * XST];             // perm [row][k xpart]
__device__ __align__(128) __half g_xbk[(size_t)T_STEPS * BATCH * XST];  // [t][b][k]
__device__ __align__(128) float  g_xp [(size_t)T_STEPS * 3072 * 256];   // [t][p][b]
__device__ __align__(128) __half g_hall[(size_t)(T_STEPS + 1) * BATCH * HID]; // [slice][b][k]
__device__ float g_bias[3072];
__device__ float g_WdecT[HID * OUTD];
__device__ unsigned g_barcnt;
__device__ unsigned g_bargen;

// ---------------- helpers ----------------
__device__ __forceinline__ uint32_t smem_u32(const void* p) {
    uint32_t a;
    asm("{ .reg .u64 t; cvta.to.shared.u64 t, %1; cvt.u32.u64 %0, t; }" : "=r"(a) : "l"(p));
    return a;
}
__device__ __forceinline__ void cp16(uint32_t dst, const void* src) {
    asm volatile("cp.async.cg.shared.global [%0], [%1], 16;" :: "r"(dst), "l"(src));
}
__device__ __forceinline__ void cpcommit() { asm volatile("cp.async.commit_group;" ::: "memory"); }
template <int N> __device__ __forceinline__ void cpwait() {
    asm volatile("cp.async.wait_group %0;" :: "n"(N) : "memory");
}
#define LDSM4(r0, r1, r2, r3, addr) \
    asm volatile("ldmatrix.sync.aligned.m8n8.x4.shared.b16 {%0,%1,%2,%3}, [%4];" \
        : "=r"(r0), "=r"(r1), "=r"(r2), "=r"(r3) : "r"(addr))
__device__ __forceinline__ void mma16(float* d, const uint32_t* a, const uint32_t* b) {
    asm volatile("mma.sync.aligned.m16n8k16.row.col.f32.f16.f16.f32 "
        "{%0,%1,%2,%3}, {%4,%5,%6,%7}, {%8,%9}, {%0,%1,%2,%3};"
        : "+f"(d[0]), "+f"(d[1]), "+f"(d[2]), "+f"(d[3])
        : "r"(a[0]), "r"(a[1]), "r"(a[2]), "r"(a[3]), "r"(b[0]), "r"(b[1]));
}
__device__ __forceinline__ float tanha(float x) {
    float y; asm("tanh.approx.f32 %0, %1;" : "=f"(y) : "f"(x)); return y;
}
__device__ __forceinline__ float sigm(float x) { return fmaf(0.5f, tanha(0.5f * x), 0.5f); }

// ---------------- grid barrier (128 CTAs, all resident at 1/SM) --------------
__device__ __forceinline__ void gridbar() {
    __syncthreads();
    if (threadIdx.x == 0) {
        __threadfence();
        unsigned gen = *(volatile unsigned*)&g_bargen;
        if (atomicAdd(&g_barcnt, 1u) == NCTA - 1u) {
            atomicExch(&g_barcnt, 0u);
            __threadfence();
            atomicAdd(&g_bargen, 1u);
        } else {
            while (*(volatile unsigned*)&g_bargen == gen) { }
        }
        __threadfence();
    }
    __syncthreads();
}

// ---------------- prep kernels ----------------
// perm row p: rt = p/96, j = p%96, wn = j/32, jj = j%32, nt = jj/8, ul = jj%8
//   gate = nt (i,f,g,o) ; unit = rt*24 + wn*8 + ul
__device__ __forceinline__ int perm_to_orig(int p) {
    int rt = p / 96, j = p % 96;
    int wn = j >> 5, jj = j & 31, nt = jj >> 3, ul = jj & 7;
    return nt * HID + rt * 24 + wn * 8 + ul;
}
__global__ void prep_w_kernel(const float* __restrict__ Wih, const float* __restrict__ Whh,
                              const float* __restrict__ bih, const float* __restrict__ bhh) {
    int idx = blockIdx.x * blockDim.x + threadIdx.x;
    if (idx < 3072) {
        int orig = perm_to_orig(idx);
        g_bias[idx] = bih[orig] + bhh[orig];
    }
    for (size_t ee = idx; ee < (size_t)3072 * HID; ee += (size_t)gridDim.x * blockDim.x) {
        int p = (int)(ee / HID), k = (int)(ee % HID);
        int orig = perm_to_orig(p);
        g_Wp[ee] = __float2half_rn(Whh[(size_t)orig * HID + k]);
    }
    for (size_t ee = idx; ee < (size_t)3072 * XST; ee += (size_t)gridDim.x * blockDim.x) {
        int p = (int)(ee / XST), k = (int)(ee % XST);
        int orig = perm_to_orig(p);
        g_Wxp[ee] = (k < IN_DIMV) ? __float2half_rn(Wih[(size_t)orig * IN_DIMV + k])
                                  : __ushort_as_half(0);
    }
}
// also zeroes h slice 0
__global__ void prep_x_kernel(const float* __restrict__ seq) {
    for (size_t e = blockIdx.x * blockDim.x + threadIdx.x;
         e < (size_t)T_STEPS * BATCH * XST; e += (size_t)gridDim.x * blockDim.x) {
        int k = (int)(e % XST);
        size_t tb = e / XST;
        g_xbk[e] = (k < IN_DIMV) ? __float2half_rn(seq[tb * IN_DIMV + k]) : __ushort_as_half(0);
        if (e < BATCH * HID) g_hall[e] = __ushort_as_half(0);
    }
}
__global__ void transpose_wdec_kernel(const float* __restrict__ Wdec) {
    __shared__ float tile[32][33];
    int k0 = blockIdx.x * 32, o0 = blockIdx.y * 32;
    int tx = threadIdx.x, ty = threadIdx.y;
    #pragma unroll
    for (int i = 0; i < 32; i += 8)
        tile[ty + i][tx] = Wdec[(size_t)(o0 + ty + i) * HID + k0 + tx];
    __syncthreads();
    #pragma unroll
    for (int i = 0; i < 32; i += 8)
        g_WdecT[(size_t)(k0 + ty + i) * OUTD + o0 + tx] = tile[tx][ty + i];
}

// ---------------- xproj GEMM: g_xp[t][p][b] = Wx * x ----------------
__global__ void __launch_bounds__(256) xproj_kernel() {
    __shared__ __half sX[128 * 72];
    __shared__ __half sWx[64 * WXS];
    const int tid = threadIdx.x, lane = tid & 31, wid = tid >> 5;
    const int wm = wid & 3, wn = wid >> 2;
    const int tile = blockIdx.x >> 1, bHalf = blockIdx.x & 1, t = blockIdx.y;
    const int q = lane >> 2, rlk = lane & 3;

    for (int i = tid; i < 64 * 24; i += 256) {
        int r = i / 24, s = i % 24;
        *(uint4*)(sWx + r * WXS + s * 8) =
            *(const uint4*)(g_Wxp + (size_t)(tile * 64 + r) * XST + s * 8);
    }

    float d[2][4][4];
    #pragma unroll
    for (int mt = 0; mt < 2; mt++)
        #pragma unroll
        for (int nt = 0; nt < 4; nt++)
            #pragma unroll
            for (int j = 0; j < 4; j++) d[mt][nt][j] = 0.f;

    for (int c = 0; c < 3; c++) {
        __syncthreads();
        #pragma unroll
        for (int j = 0; j < 4; j++) {
            int s = j * 256 + tid, row = s >> 3, seg = s & 7;
            *(uint4*)(sX + row * 72 + seg * 8) =
                *(const uint4*)(g_xbk + ((size_t)t * BATCH + bHalf * 128 + row) * XST
                                + c * 64 + seg * 8);
        }
        __syncthreads();
        #pragma unroll
        for (int ks = 0; ks < 4; ks++) {
            const int kb = ks * 16, kw = c * 64 + kb;
            uint32_t a[2][4], b[4][2];
            #pragma unroll
            for (int mt = 0; mt < 2; mt++) {
                const int m0 = wm * 32 + mt * 16 + q;
                a[mt][0] = *(const uint32_t*)(sX + (m0)     * 72 + kb + 2 * rlk);
                a[mt][1] = *(const uint32_t*)(sX + (m0 + 8) * 72 + kb + 2 * rlk);
                a[mt][2] = *(const uint32_t*)(sX + (m0)     * 72 + kb + 2 * rlk + 8);
                a[mt][3] = *(const uint32_t*)(sX + (m0 + 8) * 72 + kb + 2 * rlk + 8);
            }
            #pragma unroll
            for (int nt = 0; nt < 4; nt++) {
                const int n0 = wn * 32 + nt * 8 + q;
                b[nt][0] = *(const uint32_t*)(sWx + n0 * WXS + kw + 2 * rlk);
                b[nt][1] = *(const uint32_t*)(sWx + n0 * WXS + kw + 2 * rlk + 8);
            }
            #pragma unroll
            for (int mt = 0; mt < 2; mt++)
                #pragma unroll
                for (int nt = 0; nt < 4; nt++)
                    mma16(d[mt][nt], a[mt], b[nt]);
        }
    }

    const size_t xb = ((size_t)t * 3072 + tile * 64) * 256;
    #pragma unroll
    for (int mt = 0; mt < 2; mt++)
        #pragma unroll
        for (int nt = 0; nt < 4; nt++)
            #pragma unroll
            for (int j = 0; j < 4; j++) {
                int col = wn * 32 + nt * 8 + 2 * rlk + (j & 1);
                int bb  = bHalf * 128 + wm * 32 + mt * 16 + q + 8 * (j >> 1);
                g_xp[xb + (size_t)col * 256 + bb] = d[mt][nt][j];
            }
}

// ---------------- persistent fp16 tensor-core LSTM (128 CTAs) ---------------
__global__ void __launch_bounds__(THREADS, 1) lstm_mma_kernel() {
    extern __shared__ char smc[];
    __half* sW = (__half*)smc;                      // [96][776]
    const uint32_t sWu  = smem_u32(smc);
    const uint32_t sStU = sWu + SM_W_B;

    const int tid = threadIdx.x, lane = tid & 31, wid = tid >> 5;
    const int wm = wid & 3, wn = wid >> 2;          // 4 batch-warps(16) x 3 row-warps(32)
    const int cta = blockIdx.x, rt = cta >> 2, bTile = cta & 3;
    const int q = lane >> 2, rlk = lane & 3;
    const int gu0 = rt * 24 + wn * 8 + 2 * rlk;     // global unit pair base

    // resident W tile: 96 rows x 768 -> stride 776
    for (int i = tid; i < 96 * 96; i += THREADS) {
        int r = i / 96, s = i % 96;
        *(uint4*)(sW + r * WST + s * 8) =
            *(const uint4*)(g_Wp + (size_t)(rt * 96 + r) * HID + s * 8);
    }

    float br[4][2];                                  // [gate][unit-local e]
    #pragma unroll
    for (int nt = 0; nt < 4; nt++)
        #pragma unroll
        for (int e = 0; e < 2; e++)
            br[nt][e] = g_bias[rt * 96 + wn * 32 + nt * 8 + 2 * rlk + e];

    float cst[4];                                    // (h,e)
    #pragma unroll
    for (int i = 0; i < 4; i++) cst[i] = 0.f;

    // cp.async: 768 x 16B per chunk / 384 threads = 2 each
    int rowC[2], segC[2];
    #pragma unroll
    for (int j = 0; j < 2; j++) { int e = j * THREADS + tid; rowC[j] = e / 12; segC[j] = e % 12; }
    // ldmatrix per-lane byte offsets
    const int la = lane;
    const uint32_t offA  = ((wm * 16 + (la & 7) + ((la >> 3) & 1) * 8) * AST
                            + ((la >> 4) & 1) * 8) * 2;
    const uint32_t offB0 = sWu + ((wn * 32 + (la & 7) + ((la >> 4) & 1) * 8) * WST
                            + ((la >> 3) & 1) * 8) * 2;
    const uint32_t offB1 = offB0 + 16 * WST * 2;

    float d[4][4];
    auto load_xp = [&](int tt) {
        const float* xp = g_xp + ((size_t)tt * 3072 + rt * 96) * 256;
        #pragma unroll
        for (int nt = 0; nt < 4; nt++)
            #pragma unroll
            for (int j = 0; j < 4; j++) {
                int col = wn * 32 + nt * 8 + 2 * rlk + (j & 1);
                int bb  = bTile * 64 + wm * 16 + q + 8 * (j >> 1);
                d[nt][j] = __ldg(xp + (size_t)col * 256 + bb);
            }
    };

    __syncthreads();
    load_xp(0);

    for (int t = 0; t < T_STEPS; t++) {
        const __half* hsrc = g_hall + (size_t)(t * BATCH + bTile * 64) * HID;

        auto issue = [&](int c) {
            const uint32_t dst0 = sStU + (c % 3) * STAGE_B;
            const __half* src = hsrc + c * CHUNK;
            #pragma unroll
            for (int j = 0; j < 2; j++)
                cp16(dst0 + (rowC[j] * AST + segC[j] * 8) * 2,
                     src + (size_t)rowC[j] * HID + segC[j] * 8);
            cpcommit();
        };

        issue(0); issue(1);
        for (int c = 0; c < NCHK; c++) {
            if (c < NCHK - 1) cpwait<1>(); else cpwait<0>();
            __syncthreads();
            if (c + 2 < NCHK) issue(c + 2);

            const uint32_t sb = sStU + (c % 3) * STAGE_B;
            const uint32_t wb = c * (CHUNK * 2);
            #pragma unroll
            for (int ks = 0; ks < 6; ks++) {
                uint32_t a[4], b[4][2];
                LDSM4(a[0], a[1], a[2], a[3], sb + offA + ks * 32);
                LDSM4(b[0][0], b[0][1], b[1][0], b[1][1], offB0 + wb + ks * 32);
                LDSM4(b[2][0], b[2][1], b[3][0], b[3][1], offB1 + wb + ks * 32);
                #pragma unroll
                for (int nt = 0; nt < 4; nt++)
                    mma16(d[nt], a, b[nt]);
            }
        }

        // register epilogue: d[nt][2h+e] = gate nt of unit (2rlk+e), batch row h
        __half* hdst = g_hall + (size_t)(t + 1) * (BATCH * HID);
        #pragma unroll
        for (int h = 0; h < 2; h++) {
            float ho[2];
            #pragma unroll
            for (int e = 0; e < 2; e++) {
                float xi = d[0][2 * h + e] + br[0][e];
                float xf = d[1][2 * h + e] + br[1][e];
                float xg = d[2][2 * h + e] + br[2][e];
                float xo = d[3][2 * h + e] + br[3][e];
                const int ci = h * 2 + e;
                float cv = fmaf(sigm(xf), cst[ci], sigm(xi) * tanha(xg));
                cst[ci] = cv;
                ho[e] = sigm(xo) * tanha(cv);
            }
            const int bb = bTile * 64 + wm * 16 + q + 8 * h;
            *(__half2*)(hdst + (size_t)bb * HID + gu0) = __floats2half2_rn(ho[0], ho[1]);
        }
        if (t + 1 < T_STEPS) load_xp(t + 1);   // hidden behind barrier
        gridbar();
    }
}

// ---------------- decoder GEMM: out[t][b][o], h from g_hall fp16 ------------
__global__ void __launch_bounds__(256)
decode_kernel(const float* __restrict__ bdec, float* __restrict__ out) {
    __shared__ float wt[KTILE * 32];
    const int og = blockIdx.x, t = blockIdx.y, tid = threadIdx.x;
    const __half* hrow = g_hall + ((size_t)(t + DEC_T + 1) * BATCH + tid) * HID;
    float acc[32];
    #pragma unroll
    for (int i = 0; i < 32; i++) acc[i] = 0.f;
    for (int kt = 0; kt < HID / KTILE; kt++) {
        const int k0 = kt * KTILE;
        #pragma unroll
        for (int i = 0; i < 4; i++) {
            int e = i * 256 + tid, kk = e >> 5, oo = e & 31;
            wt[e] = g_WdecT[(size_t)(k0 + kk) * OUTD + og * 32 + oo];
        }
        __syncthreads();
        __half hh[KTILE];
        #pragma unroll
        for (int i = 0; i < 4; i++)
            *(uint4*)&hh[i * 8] = *(const uint4*)(hrow + k0 + i * 8);
        #pragma unroll 8
        for (int kk = 0; kk < KTILE; kk++) {
            float hv = __half2float(hh[kk]);
            #pragma unroll
            for (int o4 = 0; o4 < 8; o4++) {
                float4 w = *(const float4*)&wt[kk * 32 + o4 * 4];
                acc[o4 * 4 + 0] += hv * w.x;  acc[o4 * 4 + 1] += hv * w.y;
                acc[o4 * 4 + 2] += hv * w.z;  acc[o4 * 4 + 3] += hv * w.w;
            }
        }
        __syncthreads();
    }
    size_t ob = ((size_t)t * BATCH + tid) * OUTD + og * 32;
    #pragma unroll
    for (int o4 = 0; o4 < 8; o4++) {
        float4 r;
        r.x = acc[o4 * 4 + 0] + bdec[og * 32 + o4 * 4 + 0];
        r.y = acc[o4 * 4 + 1] + bdec[og * 32 + o4 * 4 + 1];
        r.z = acc[o4 * 4 + 2] + bdec[og * 32 + o4 * 4 + 2];
        r.w = acc[o4 * 4 + 3] + bdec[og * 32 + o4 * 4 + 3];
        *(float4*)&out[ob + o4 * 4] = r;
    }
}

// ---------------- launch (lstm at launch index 3 for ncu capture) -----------
extern "C" void kernel_launch(void* const* d_in, const int* in_sizes, int n_in,
                              void* d_out, int out_size) {
    const float* seq  = (const float*)d_in[0];
    const float* Wih  = (const float*)d_in[1];
    const float* Whh  = (const float*)d_in[2];
    const float* bih  = (const float*)d_in[3];
    const float* bhh  = (const float*)d_in[4];
    const float* Wdec = (const float*)d_in[5];
    const float* bdec = (const float*)d_in[6];
    float* out = (float*)d_out;

    cudaFuncSetAttribute(lstm_mma_kernel, cudaFuncAttributeMaxDynamicSharedMemorySize, SMEM_SZ);

    prep_w_kernel<<<512, 256>>>(Wih, Whh, bih, bhh);        // 0
    prep_x_kernel<<<2048, 256>>>(seq);                      // 1
    xproj_kernel<<<dim3(96, T_STEPS), 256>>>();             // 2
    lstm_mma_kernel<<<NCTA, THREADS, SMEM_SZ>>>();          // 3  <- ncu slot
    dim3 tb(32, 8);
    transpose_wdec_kernel<<<dim3(HID / 32, OUTD / 32), tb>>>(Wdec);  // 4
    decode_kernel<<<dim3(4, DEC_T), 256>>>(bdec, out);      // 5
}